// round 3
// baseline (speedup 1.0000x reference)
#include <cuda_runtime.h>
#include <cuda_bf16.h>

// Problem constants
#define N_ROWS   262144
#define K_CODES  1024
#define D_DIM    64
#define M_TILE   128     // rows per block
#define KC       128     // codebook chunk per smem stage

// ||c_k||^2 computed with the reference-emulating halving tree
__device__ float g_csq[K_CODES];

// Emulate jnp.sum(v*v, axis=-1) for a 64-vector, XLA-GPU row-reduce order:
// lane l: v[l]^2 + v[l+32]^2, then halving tree over strides 16,8,4,2,1.
// All ops forced round-to-nearest, no FMA contraction.
__device__ __forceinline__ float sq_sum_tree64(const float* v, int stride) {
    float s[32];
#pragma unroll
    for (int l = 0; l < 32; l++) {
        float a = v[l * stride];
        float b = v[(l + 32) * stride];
        s[l] = __fadd_rn(__fmul_rn(a, a), __fmul_rn(b, b));
    }
#pragma unroll
    for (int off = 16; off >= 1; off >>= 1) {
#pragma unroll
        for (int l = 0; l < 16; l++) {
            if (l < off) s[l] = __fadd_rn(s[l], s[l + off]);
        }
    }
    return s[0];
}

__global__ void precompute_csq_kernel(const float* __restrict__ cb) {
    int k = blockIdx.x * blockDim.x + threadIdx.x;
    if (k < K_CODES) {
        g_csq[k] = sq_sum_tree64(cb + (size_t)k * D_DIM, 1);
    }
}

// Fused kernel: GEMM(x, c^T) with argmin epilogue + gather + residual.
// Block: 256 threads (tx = t&15 -> 16 k-groups, ty = t>>4 -> 16 row-groups).
// Each thread: 8 rows (ty*8..ty*8+7) x 8 codes (k = chunk + tx + 16*j).
extern "C" __global__ void __launch_bounds__(256)
vq_argmin_kernel(const float* __restrict__ X,
                 const float* __restrict__ C,
                 float* __restrict__ out_idx,   // [N]   (float-encoded int)
                 float* __restrict__ out_res,   // [N,D]
                 float* __restrict__ out_cb)    // [N,D]
{
    extern __shared__ float smem[];
    // As[d][row] : 64 x 128  (d-major so row-dim loads vectorize)
    // Bs[d][k]   : 64 x 128
    float (*As)[M_TILE] = (float (*)[M_TILE])smem;
    float (*Bs)[KC]     = (float (*)[KC])(smem + D_DIM * M_TILE);
    float* xsq_sh       = smem + D_DIM * M_TILE + D_DIM * KC;          // [128]
    float* csq_sh       = xsq_sh + M_TILE;                             // [128]
    int*   best_sh      = (int*)(csq_sh + KC);                         // [128]

    const int t  = threadIdx.x;
    const int tx = t & 15;
    const int ty = t >> 4;
    const int m0 = blockIdx.x * M_TILE;

    // ---- Load A tile (128 rows x 64 d) transposed into smem ----
    {
        const float4* X4 = (const float4*)(X + (size_t)m0 * D_DIM);
#pragma unroll
        for (int i = 0; i < 8; i++) {
            int f   = t + i * 256;   // float4 index, 0..2047 (coalesced)
            int row = f >> 4;        // 16 float4 per row
            int d4  = f & 15;
            float4 v = X4[f];
            As[d4 * 4 + 0][row] = v.x;
            As[d4 * 4 + 1][row] = v.y;
            As[d4 * 4 + 2][row] = v.z;
            As[d4 * 4 + 3][row] = v.w;
        }
    }
    __syncthreads();

    // ---- x_sq per row, reference-emulating order ----
    // As[d][t]: for fixed d, lanes t..t+31 hit distinct banks -> conflict-free.
    if (t < M_TILE) {
        float s[32];
#pragma unroll
        for (int l = 0; l < 32; l++) {
            float a = As[l][t];
            float b = As[l + 32][t];
            s[l] = __fadd_rn(__fmul_rn(a, a), __fmul_rn(b, b));
        }
#pragma unroll
        for (int off = 16; off >= 1; off >>= 1) {
#pragma unroll
            for (int l = 0; l < 16; l++) {
                if (l < off) s[l] = __fadd_rn(s[l], s[l + off]);
            }
        }
        xsq_sh[t] = s[0];
    }

    float best_s[8];
    int   best_k[8];
#pragma unroll
    for (int i = 0; i < 8; i++) { best_s[i] = 3.0e38f; best_k[i] = 0; }

    for (int kc0 = 0; kc0 < K_CODES; kc0 += KC) {
        __syncthreads();  // protect Bs/csq before overwrite (also covers xsq write on iter 0)
        // ---- Load B chunk (128 codes x 64 d) transposed ----
        {
            const float4* C4 = (const float4*)(C + (size_t)kc0 * D_DIM);
#pragma unroll
            for (int i = 0; i < 8; i++) {
                int f   = t + i * 256;
                int row = f >> 4;
                int d4  = f & 15;
                float4 v = C4[f];
                Bs[d4 * 4 + 0][row] = v.x;
                Bs[d4 * 4 + 1][row] = v.y;
                Bs[d4 * 4 + 2][row] = v.z;
                Bs[d4 * 4 + 3][row] = v.w;
            }
            if (t < KC) csq_sh[t] = g_csq[kc0 + t];
        }
        __syncthreads();

        float acc[8][8];
#pragma unroll
        for (int i = 0; i < 8; i++)
#pragma unroll
            for (int j = 0; j < 8; j++) acc[i][j] = 0.f;

        // xc: sequential-d FMA accumulation (d = 0..63 ascending)
#pragma unroll 8
        for (int d = 0; d < D_DIM; d++) {
            // rows: 2x LDS.128 (two distinct addresses per warp -> broadcast)
            float4 a0 = *(const float4*)&As[d][ty * 8];
            float4 a1 = *(const float4*)&As[d][ty * 8 + 4];
            float a[8] = {a0.x, a0.y, a0.z, a0.w, a1.x, a1.y, a1.z, a1.w};
            // codes: stride-16 k mapping -> conflict-free
            float b[8];
#pragma unroll
            for (int j = 0; j < 8; j++) b[j] = Bs[d][tx + 16 * j];
#pragma unroll
            for (int i = 0; i < 8; i++)
#pragma unroll
                for (int j = 0; j < 8; j++)
                    acc[i][j] = fmaf(a[i], b[j], acc[i][j]);
        }

        // ---- Reference-emulated score: fl(fl(x_sq - 2*xc) + c_sq), argMIN ----
        float xs[8];
#pragma unroll
        for (int i = 0; i < 8; i++) xs[i] = xsq_sh[ty * 8 + i];
        float cs[8];
#pragma unroll
        for (int j = 0; j < 8; j++) cs[j] = csq_sh[tx + 16 * j];
#pragma unroll
        for (int i = 0; i < 8; i++) {
#pragma unroll
            for (int j = 0; j < 8; j++) {
                float s = __fadd_rn(__fsub_rn(xs[i], 2.0f * acc[i][j]), cs[j]);
                int   k = kc0 + tx + 16 * j;
                if (s < best_s[i] || (s == best_s[i] && k < best_k[i])) {
                    best_s[i] = s; best_k[i] = k;
                }
            }
        }
    }

    // ---- Reduce argmin across the 16 tx lanes sharing the same rows ----
    // jnp.argmin tie-break: lowest index wins on exact equality.
#pragma unroll
    for (int off = 8; off; off >>= 1) {
#pragma unroll
        for (int i = 0; i < 8; i++) {
            float os = __shfl_xor_sync(0xffffffffu, best_s[i], off);
            int   ok = __shfl_xor_sync(0xffffffffu, best_k[i], off);
            if (os < best_s[i] || (os == best_s[i] && ok < best_k[i])) {
                best_s[i] = os; best_k[i] = ok;
            }
        }
    }
    if (tx == 0) {
#pragma unroll
        for (int i = 0; i < 8; i++) best_sh[ty * 8 + i] = best_k[i];
    }
    __syncthreads();

    // ---- Epilogue: gather codebook rows, write idx / residual / embedding ----
#pragma unroll
    for (int i = 0; i < (M_TILE * D_DIM) / 256; i++) {  // 32 iters
        int f   = t + i * 256;
        int row = f >> 6;   // /64
        int d   = f & 63;
        int bk  = best_sh[row];
        size_t g = (size_t)(m0 + row) * D_DIM + d;
        float cv = __ldg(&C[(size_t)bk * D_DIM + d]);
        float xv = __ldg(&X[g]);   // coalesced re-read
        out_cb[g]  = cv;
        out_res[g] = __fsub_rn(xv, cv);
    }
    if (t < M_TILE) {
        out_idx[m0 + t] = (float)best_sh[t];
    }
}

extern "C" void kernel_launch(void* const* d_in, const int* in_sizes, int n_in,
                              void* d_out, int out_size) {
    const float* X = (const float*)d_in[0];  // previous_residual [N, D]
    const float* C = (const float*)d_in[1];  // codebook_embeddings [K, D]

    float* out_idx = (float*)d_out;                              // [N]
    float* out_res = out_idx + N_ROWS;                           // [N*D]
    float* out_cb  = out_res + (size_t)N_ROWS * D_DIM;           // [N*D]

    const int smem_bytes = (D_DIM * M_TILE + D_DIM * KC + M_TILE + KC + M_TILE) * 4;
    cudaFuncSetAttribute(vq_argmin_kernel,
                         cudaFuncAttributeMaxDynamicSharedMemorySize, smem_bytes);

    precompute_csq_kernel<<<(K_CODES + 255) / 256, 256>>>(C);
    vq_argmin_kernel<<<N_ROWS / M_TILE, 256, smem_bytes>>>(X, C, out_idx, out_res, out_cb);
}

// round 5
// speedup vs baseline: 1.7722x; 1.7722x over previous
#include <cuda_runtime.h>
#include <cuda_bf16.h>
#include <cstdint>

// ---------------- Problem constants ----------------
#define N_ROWS     262144
#define K_CODES    1024
#define D_DIM      64
#define M_TILE     128                  // rows per CTA
#define CHUNK      64                   // codes per streamed chunk
#define NUM_CHUNKS (K_CODES / CHUNK)    // 16
#define KCOLS      208                  // [xh(64)|xh(64)|xl(64)|bias(2)|pad(14)]
#define NUM_KS     (KCOLS / 16)         // 13
#define ROWB       432                  // smem row stride bytes (216 bf16): 16B-aligned, LDSM conflict-free
#define TAU        4e-4f                // certification threshold (score units)

// ---------------- Static scratch ----------------
__device__ float g_csq[K_CODES];
__device__ __align__(16) __nv_bfloat16 g_Bg[K_CODES * KCOLS]; // split codebook + bias cols
__device__ int g_namb;
__device__ int g_amb_rows[N_ROWS];

// ---------------- Helpers ----------------
__device__ __forceinline__ uint32_t smem_u32(const void* p) {
    uint32_t a;
    asm("{ .reg .u64 t; cvta.to.shared.u64 t, %1; cvt.u32.u64 %0, t; }" : "=r"(a) : "l"(p));
    return a;
}
#define LDSM4(r0, r1, r2, r3, a)                                                    \
    asm volatile("ldmatrix.sync.aligned.m8n8.x4.shared.b16 {%0,%1,%2,%3}, [%4];"    \
                 : "=r"(r0), "=r"(r1), "=r"(r2), "=r"(r3) : "r"(a))
#define MMA16816(d, a, b0v, b1v)                                                    \
    asm volatile("mma.sync.aligned.m16n8k16.row.col.f32.bf16.bf16.f32 "             \
                 "{%0,%1,%2,%3},{%4,%5,%6,%7},{%8,%9},{%0,%1,%2,%3};"               \
                 : "+f"((d)[0]), "+f"((d)[1]), "+f"((d)[2]), "+f"((d)[3])           \
                 : "r"((a)[0]), "r"((a)[1]), "r"((a)[2]), "r"((a)[3]),              \
                   "r"(b0v), "r"(b1v))
#define CP_ASYNC16(dst, src) asm volatile("cp.async.cg.shared.global [%0], [%1], 16;" :: "r"(dst), "l"(src))
#define CP_COMMIT()          asm volatile("cp.async.commit_group;" ::: "memory")
#define CP_WAIT1()           asm volatile("cp.async.wait_group 1;" ::: "memory")
#define CP_WAIT0()           asm volatile("cp.async.wait_group 0;" ::: "memory")

__device__ __forceinline__ uint32_t pack_bf2(__nv_bfloat16 a, __nv_bfloat16 b) {
    __nv_bfloat162 t(a, b);
    return *reinterpret_cast<uint32_t*>(&t);
}

// ---------------- Exact reference-order arithmetic (bit-validated in R3) ----------------
__device__ __forceinline__ float sq_sum_tree64(const float* v) {
    float s[32];
#pragma unroll
    for (int l = 0; l < 32; l++) {
        float a = v[l], b = v[l + 32];
        s[l] = __fadd_rn(__fmul_rn(a, a), __fmul_rn(b, b));
    }
#pragma unroll
    for (int off = 16; off >= 1; off >>= 1)
#pragma unroll
        for (int l = 0; l < 16; l++)
            if (l < off) s[l] = __fadd_rn(s[l], s[l + off]);
    return s[0];
}

__global__ void zero_kernel() { g_namb = 0; }

// ---------------- Prep: exact csq + split codebook with folded bias ----------------
__global__ void prep_kernel(const float* __restrict__ Cb) {
    int k = blockIdx.x * blockDim.x + threadIdx.x;
    if (k >= K_CODES) return;
    const float* c = Cb + (size_t)k * D_DIM;
    float csq = sq_sum_tree64(c);
    g_csq[k] = csq;
    __nv_bfloat16* o = g_Bg + (size_t)k * KCOLS;
#pragma unroll 8
    for (int d = 0; d < D_DIM; d++) {
        float x = c[d];
        __nv_bfloat16 h = __float2bfloat16_rn(x);
        __nv_bfloat16 l = __float2bfloat16_rn(x - __bfloat162float(h));
        o[d]       = h;   // pairs with xh
        o[64 + d]  = l;   // pairs with xh
        o[128 + d] = h;   // pairs with xl
    }
    float bias = -0.5f * csq;
    __nv_bfloat16 bh = __float2bfloat16_rn(bias);
    __nv_bfloat16 bl = __float2bfloat16_rn(bias - __bfloat162float(bh));
    o[192] = bh;          // pairs with x-side 1.0
    o[193] = bl;          // pairs with x-side 1.0
#pragma unroll
    for (int d = 194; d < KCOLS; d++) o[d] = __float2bfloat16_rn(0.f);
}

// ---------------- Screen kernel: HMMA bf16 split-GEMM + top-2 certify ----------------
// smem: A [128 x 216 bf16] @0 (55296B), B double buffer [64 x 216] x2 (27648B each), best_sh
#define SM_A   0u
#define SM_B   55296u
#define SM_BK  110592u
#define SM_TOTAL 111104u

extern "C" __global__ void __launch_bounds__(256, 2)
vq_screen_kernel(const float* __restrict__ X, const float* __restrict__ Cb,
                 float* __restrict__ out_idx, float* __restrict__ out_res,
                 float* __restrict__ out_cb) {
    extern __shared__ __align__(128) char smem[];
    const uint32_t sb = smem_u32(smem);
    const int t = threadIdx.x;
    const int w = t >> 5, l = t & 31;
    const int wr0 = w * 16;                 // warp's row base
    const int m0 = blockIdx.x * M_TILE;
    int* best_sh = (int*)(smem + SM_BK);

    // ---- prologue: stream B chunks 0,1 via cp.async ----
    {
        const uint4* src = reinterpret_cast<const uint4*>(g_Bg);  // 13 uint4 per code... (208*2/16=26)
#pragma unroll 1
        for (int cc = 0; cc < 2; cc++) {
            const uint4* s2 = src + (size_t)cc * CHUNK * 26;
            uint32_t dstb = sb + SM_B + cc * (CHUNK * ROWB);
            for (int idx = t; idx < CHUNK * 26; idx += 256) {
                int code = idx / 26, u = idx - code * 26;
                CP_ASYNC16(dstb + code * ROWB + u * 16, s2 + idx);
            }
            CP_COMMIT();
        }
    }

    // ---- build A' = [xh|xh|xl|1,1,0...] into smem (overlaps the copies) ----
    {
        const float4* X4 = (const float4*)(X + (size_t)m0 * D_DIM);
#pragma unroll
        for (int i = 0; i < 8; i++) {
            int f = t + i * 256;             // 2048 float4
            int row = f >> 4, d = (f & 15) * 4;
            float4 v = X4[f];
            __nv_bfloat16 h0 = __float2bfloat16_rn(v.x), h1 = __float2bfloat16_rn(v.y);
            __nv_bfloat16 h2 = __float2bfloat16_rn(v.z), h3 = __float2bfloat16_rn(v.w);
            __nv_bfloat16 l0 = __float2bfloat16_rn(v.x - __bfloat162float(h0));
            __nv_bfloat16 l1 = __float2bfloat16_rn(v.y - __bfloat162float(h1));
            __nv_bfloat16 l2 = __float2bfloat16_rn(v.z - __bfloat162float(h2));
            __nv_bfloat16 l3 = __float2bfloat16_rn(v.w - __bfloat162float(h3));
            uint2 hv = make_uint2(pack_bf2(h0, h1), pack_bf2(h2, h3));
            uint2 lv = make_uint2(pack_bf2(l0, l1), pack_bf2(l2, l3));
            char* rp = smem + SM_A + row * ROWB;
            *reinterpret_cast<uint2*>(rp + d * 2)         = hv;
            *reinterpret_cast<uint2*>(rp + 128 + d * 2)   = hv;
            *reinterpret_cast<uint2*>(rp + 256 + d * 2)   = lv;
        }
        if (t < M_TILE) {                    // bias + pad cols 192..207
            char* rp = smem + SM_A + t * ROWB;
            *reinterpret_cast<uint2*>(rp + 384) = make_uint2(0x3F803F80u, 0u);
            *reinterpret_cast<uint2*>(rp + 392) = make_uint2(0u, 0u);
            *reinterpret_cast<uint2*>(rp + 400) = make_uint2(0u, 0u);
            *reinterpret_cast<uint2*>(rp + 408) = make_uint2(0u, 0u);
        }
    }
    __syncthreads();

    // ---- preload A fragments (13 k-steps x 4 regs) ----
    uint32_t af[NUM_KS][4];
    {
        uint32_t aAddr = sb + SM_A + (uint32_t)(wr0 + (l & 15)) * ROWB + (uint32_t)(l >> 4) * 16;
#pragma unroll
        for (int ks = 0; ks < NUM_KS; ks++)
            LDSM4(af[ks][0], af[ks][1], af[ks][2], af[ks][3], aAddr + ks * 32);
    }

    // B lane offset within a 16-code group (x4: [n0-7,k0-7][n0-7,k8-15][n8-15,k0-7][n8-15,k8-15])
    const uint32_t bLane = (uint32_t)(l & 7) * ROWB + ((uint32_t)(l >> 3) & 1) * 16 +
                           ((uint32_t)(l >> 4) & 1) * (8 * ROWB);

    // top-2 state: row q = wr0 + (l>>2) and row q+8
    float bmA1 = -3.0e38f, bmA2 = -3.0e38f, bmB1 = -3.0e38f, bmB2 = -3.0e38f;
    int bkA = 0, bkB = 0;

    for (int c = 0; c < NUM_CHUNKS; c++) {
        if (c >= NUM_CHUNKS - 2) { CP_WAIT0(); } else { CP_WAIT1(); }
        __syncthreads();

        const uint32_t bufB = sb + SM_B + (uint32_t)(c & 1) * (CHUNK * ROWB);
        float acc[8][4];
#pragma unroll
        for (int nt = 0; nt < 8; nt++)
#pragma unroll
            for (int j = 0; j < 4; j++) acc[nt][j] = 0.f;

#pragma unroll
        for (int np = 0; np < 4; np++) {           // 16 codes per pair-group
            const uint32_t bBase = bufB + (uint32_t)np * (16 * ROWB) + bLane;
#pragma unroll
            for (int ks = 0; ks < NUM_KS; ks++) {
                uint32_t b0, b1, b2, b3;
                LDSM4(b0, b1, b2, b3, bBase + ks * 32);
                MMA16816(acc[np * 2],     af[ks], b0, b1);
                MMA16816(acc[np * 2 + 1], af[ks], b2, b3);
            }
        }
        __syncthreads();   // done reading buf (before refill)

        // refill this buffer with chunk c+2
        if (c + 2 < NUM_CHUNKS) {
            const uint4* s2 = reinterpret_cast<const uint4*>(g_Bg) + (size_t)(c + 2) * CHUNK * 26;
            uint32_t dstb = sb + SM_B + (uint32_t)(c & 1) * (CHUNK * ROWB);
            for (int idx = t; idx < CHUNK * 26; idx += 256) {
                int code = idx / 26, u = idx - code * 26;
                CP_ASYNC16(dstb + code * ROWB + u * 16, s2 + idx);
            }
            CP_COMMIT();
        }

        // ---- epilogue: running top-2 / argmax (k ascending; strict > keeps lowest k) ----
#pragma unroll
        for (int nt = 0; nt < 8; nt++) {
            int k0 = c * CHUNK + nt * 8 + (l & 3) * 2;
            float v0 = acc[nt][0], v1 = acc[nt][1], v2 = acc[nt][2], v3 = acc[nt][3];
            if (v0 > bmA1) { bmA2 = bmA1; bmA1 = v0; bkA = k0; }     else bmA2 = fmaxf(bmA2, v0);
            if (v1 > bmA1) { bmA2 = bmA1; bmA1 = v1; bkA = k0 + 1; } else bmA2 = fmaxf(bmA2, v1);
            if (v2 > bmB1) { bmB2 = bmB1; bmB1 = v2; bkB = k0; }     else bmB2 = fmaxf(bmB2, v2);
            if (v3 > bmB1) { bmB2 = bmB1; bmB1 = v3; bkB = k0 + 1; } else bmB2 = fmaxf(bmB2, v3);
        }
    }

    // ---- merge across the 4 lanes of each quad (same rows, disjoint cols) ----
#pragma unroll
    for (int off = 1; off <= 2; off <<= 1) {
        float o1, o2; int ok;
        o1 = __shfl_xor_sync(0xffffffffu, bmA1, off);
        o2 = __shfl_xor_sync(0xffffffffu, bmA2, off);
        ok = __shfl_xor_sync(0xffffffffu, bkA, off);
        {
            bool bw = (o1 > bmA1) || (o1 == bmA1 && ok < bkA);
            float n2 = fmaxf(fminf(bmA1, o1), fmaxf(bmA2, o2));
            if (bw) { bmA1 = o1; bkA = ok; }
            bmA2 = n2;
        }
        o1 = __shfl_xor_sync(0xffffffffu, bmB1, off);
        o2 = __shfl_xor_sync(0xffffffffu, bmB2, off);
        ok = __shfl_xor_sync(0xffffffffu, bkB, off);
        {
            bool bw = (o1 > bmB1) || (o1 == bmB1 && ok < bkB);
            float n2 = fmaxf(fminf(bmB1, o1), fmaxf(bmB2, o2));
            if (bw) { bmB1 = o1; bkB = ok; }
            bmB2 = n2;
        }
    }
    if ((l & 3) == 0) {
        int rowA = wr0 + (l >> 2);
        int rowB = rowA + 8;
        best_sh[rowA] = bkA;
        best_sh[rowB] = bkB;
        out_idx[m0 + rowA] = (float)bkA;
        out_idx[m0 + rowB] = (float)bkB;
        if (bmA1 - bmA2 <= TAU) { int a = atomicAdd(&g_namb, 1); g_amb_rows[a] = m0 + rowA; }
        if (bmB1 - bmB2 <= TAU) { int a = atomicAdd(&g_namb, 1); g_amb_rows[a] = m0 + rowB; }
    }
    __syncthreads();

    // ---- outputs: gather + residual ----
#pragma unroll
    for (int i = 0; i < (M_TILE * D_DIM) / 256; i++) {   // 32 iters
        int f = t + i * 256;
        int row = f >> 6, d = f & 63;
        int bk = best_sh[row];
        size_t g = (size_t)(m0 + row) * D_DIM + d;
        float cv = __ldg(&Cb[(size_t)bk * D_DIM + d]);
        float xv = __ldg(&X[g]);
        out_cb[g]  = cv;
        out_res[g] = __fsub_rn(xv, cv);
    }
}

// ---------------- Exact fallback for ambiguous rows (R3-validated arithmetic) ----------------
__global__ void __launch_bounds__(128)
vq_fallback_kernel(const float* __restrict__ X, const float* __restrict__ Cb,
                   float* __restrict__ out_idx, float* __restrict__ out_res,
                   float* __restrict__ out_cb) {
    __shared__ float xrow[D_DIM];
    __shared__ float xsq_s;
    __shared__ float rs[4];
    __shared__ int rk[4];
    const int t = threadIdx.x;
    const int n = g_namb;
    for (int j = blockIdx.x; j < n; j += gridDim.x) {
        const int row = g_amb_rows[j];
        __syncthreads();
        if (t < D_DIM) xrow[t] = X[(size_t)row * D_DIM + t];
        __syncthreads();
        if (t == 0) xsq_s = sq_sum_tree64(xrow);
        __syncthreads();
        const float xsq = xsq_s;
        float bs = 3.0e38f;
        int bk = 0;
#pragma unroll
        for (int c = 0; c < K_CODES / 128; c++) {
            int k = c * 128 + t;
            const float* cr = Cb + (size_t)k * D_DIM;
            float acc = 0.f;
#pragma unroll 8
            for (int d = 0; d < D_DIM; d++) acc = fmaf(xrow[d], __ldg(&cr[d]), acc);
            float s = __fadd_rn(__fsub_rn(xsq, 2.0f * acc), g_csq[k]);
            if (s < bs) { bs = s; bk = k; }
        }
#pragma unroll
        for (int off = 16; off; off >>= 1) {
            float os = __shfl_xor_sync(0xffffffffu, bs, off);
            int ok = __shfl_xor_sync(0xffffffffu, bk, off);
            if (os < bs || (os == bs && ok < bk)) { bs = os; bk = ok; }
        }
        if ((t & 31) == 0) { rs[t >> 5] = bs; rk[t >> 5] = bk; }
        __syncthreads();
        if (t == 0) {
            for (int wi = 1; wi < 4; wi++)
                if (rs[wi] < rs[0] || (rs[wi] == rs[0] && rk[wi] < rk[0])) {
                    rs[0] = rs[wi]; rk[0] = rk[wi];
                }
            out_idx[row] = (float)rk[0];
        }
        __syncthreads();
        const int k1 = rk[0];
        if (t < D_DIM) {
            size_t g = (size_t)row * D_DIM + t;
            float cv = __ldg(&Cb[(size_t)k1 * D_DIM + t]);
            out_cb[g]  = cv;
            out_res[g] = __fsub_rn(xrow[t], cv);
        }
    }
}

// ---------------- Launch ----------------
extern "C" void kernel_launch(void* const* d_in, const int* in_sizes, int n_in,
                              void* d_out, int out_size) {
    const float* X = (const float*)d_in[0];
    const float* C = (const float*)d_in[1];
    float* out_idx = (float*)d_out;
    float* out_res = out_idx + N_ROWS;
    float* out_cb  = out_res + (size_t)N_ROWS * D_DIM;

    cudaFuncSetAttribute(vq_screen_kernel,
                         cudaFuncAttributeMaxDynamicSharedMemorySize, SM_TOTAL);

    zero_kernel<<<1, 1>>>();
    prep_kernel<<<(K_CODES + 255) / 256, 256>>>(C);
    vq_screen_kernel<<<N_ROWS / M_TILE, 256, SM_TOTAL>>>(X, C, out_idx, out_res, out_cb);
    vq_fallback_kernel<<<2048, 128>>>(X, C, out_idx, out_res, out_cb);
}

// round 6
// speedup vs baseline: 3.9781x; 2.2447x over previous
#include <cuda_runtime.h>
#include <cuda_fp16.h>
#include <cstdint>

// ---------------- Problem constants ----------------
#define N_ROWS     262144
#define K_CODES    1024
#define D_DIM      64
#define M_TILE     128                  // rows per CTA
#define CHUNK      64                   // codes per streamed chunk
#define NUM_CHUNKS (K_CODES / CHUNK)    // 16
#define KCOLS      80                   // [xh(64)|bias(2)|pad(14)] fp16
#define NUM_KS     (KCOLS / 16)         // 5
#define GROWB      160                  // global bytes per code row (80 fp16)
#define ROWB       176                  // smem row stride: (row*44)%32 all-distinct -> LDSM conflict-free
#define TAU        1.2e-3f              // certification threshold (~8.5 sigma of screen error)

// ---------------- Static scratch ----------------
__device__ float g_csq[K_CODES];
__device__ float g_Ct[D_DIM * K_CODES];                     // transposed codebook (d-major) for fallback
__device__ __align__(16) __half g_Bg[K_CODES * KCOLS];      // fp16 codebook + folded bias cols
__device__ int g_namb;
__device__ int g_amb_rows[N_ROWS];

// ---------------- Helpers ----------------
__device__ __forceinline__ uint32_t smem_u32(const void* p) {
    uint32_t a;
    asm("{ .reg .u64 t; cvta.to.shared.u64 t, %1; cvt.u32.u64 %0, t; }" : "=r"(a) : "l"(p));
    return a;
}
#define LDSM4(r0, r1, r2, r3, a)                                                    \
    asm volatile("ldmatrix.sync.aligned.m8n8.x4.shared.b16 {%0,%1,%2,%3}, [%4];"    \
                 : "=r"(r0), "=r"(r1), "=r"(r2), "=r"(r3) : "r"(a))
#define MMA16816(d, a, b0v, b1v)                                                    \
    asm volatile("mma.sync.aligned.m16n8k16.row.col.f32.f16.f16.f32 "               \
                 "{%0,%1,%2,%3},{%4,%5,%6,%7},{%8,%9},{%0,%1,%2,%3};"               \
                 : "+f"((d)[0]), "+f"((d)[1]), "+f"((d)[2]), "+f"((d)[3])           \
                 : "r"((a)[0]), "r"((a)[1]), "r"((a)[2]), "r"((a)[3]),              \
                   "r"(b0v), "r"(b1v))
#define CP_ASYNC16(dst, src) asm volatile("cp.async.cg.shared.global [%0], [%1], 16;" :: "r"(dst), "l"(src))
#define CP_COMMIT()          asm volatile("cp.async.commit_group;" ::: "memory")
#define CP_WAIT1()           asm volatile("cp.async.wait_group 1;" ::: "memory")
#define CP_WAIT0()           asm volatile("cp.async.wait_group 0;" ::: "memory")

__device__ __forceinline__ uint32_t pack_h2(__half a, __half b) {
    __half2 t(a, b);
    return *reinterpret_cast<uint32_t*>(&t);
}

// ---------------- Exact reference-order arithmetic (bit-validated in R3/R5) ----------------
__device__ __forceinline__ float sq_sum_tree64(const float* v) {
    float s[32];
#pragma unroll
    for (int l = 0; l < 32; l++) {
        float a = v[l], b = v[l + 32];
        s[l] = __fadd_rn(__fmul_rn(a, a), __fmul_rn(b, b));
    }
#pragma unroll
    for (int off = 16; off >= 1; off >>= 1)
#pragma unroll
        for (int l = 0; l < 16; l++)
            if (l < off) s[l] = __fadd_rn(s[l], s[l + off]);
    return s[0];
}

__global__ void zero_kernel() { g_namb = 0; }

// ---------------- Prep: exact csq + fp16 codebook (bias folded) + transposed copy ----------------
__global__ void prep_kernel(const float* __restrict__ Cb) {
    int k = blockIdx.x * blockDim.x + threadIdx.x;
    if (k >= K_CODES) return;
    const float* c = Cb + (size_t)k * D_DIM;
    float csq = sq_sum_tree64(c);
    g_csq[k] = csq;
    __half* o = g_Bg + (size_t)k * KCOLS;
#pragma unroll 8
    for (int d = 0; d < D_DIM; d++) {
        float x = c[d];
        o[d] = __float2half_rn(x);
        g_Ct[d * K_CODES + k] = x;      // d-major for coalesced fallback
    }
    float bias = -0.5f * csq;
    __half bh = __float2half_rn(bias);
    __half bl = __float2half_rn(bias - __half2float(bh));
    o[64] = bh;                          // pairs with x-side 1.0
    o[65] = bl;                          // pairs with x-side 1.0
#pragma unroll
    for (int d = 66; d < KCOLS; d++) o[d] = __float2half_rn(0.f);
}

// ---------------- Screen kernel: fp16 HMMA GEMM + folded bias + top-2 certify ----------------
// smem: A [128 x ROWB] @0 (22528B), B double buffer [64 x ROWB] x2 (11264B each), best_sh
#define SM_A   0u
#define SM_B   22528u
#define SM_BK  45056u
#define SM_TOTAL 45568u

extern "C" __global__ void __launch_bounds__(256, 4)
vq_screen_kernel(const float* __restrict__ X, const float* __restrict__ Cb,
                 float* __restrict__ out_idx, float* __restrict__ out_res,
                 float* __restrict__ out_cb) {
    extern __shared__ __align__(128) char smem[];
    const uint32_t sb = smem_u32(smem);
    const int t = threadIdx.x;
    const int w = t >> 5, l = t & 31;
    const int wr0 = w * 16;                 // warp's row base
    const int m0 = blockIdx.x * M_TILE;
    int* best_sh = (int*)(smem + SM_BK);

    // ---- prologue: stream B chunks 0,1 via cp.async (10 uint4 per code) ----
    {
        const uint4* src = reinterpret_cast<const uint4*>(g_Bg);
#pragma unroll 1
        for (int cc = 0; cc < 2; cc++) {
            const uint4* s2 = src + (size_t)cc * CHUNK * 10;
            uint32_t dstb = sb + SM_B + cc * (CHUNK * ROWB);
            for (int idx = t; idx < CHUNK * 10; idx += 256) {
                int code = idx / 10, u = idx - code * 10;
                CP_ASYNC16(dstb + code * ROWB + u * 16, s2 + idx);
            }
            CP_COMMIT();
        }
    }

    // ---- build A' = [xh(64)|1,1|0-pad] into smem (overlaps copies) ----
    {
        const float4* X4 = (const float4*)(X + (size_t)m0 * D_DIM);
#pragma unroll
        for (int i = 0; i < 8; i++) {
            int f = t + i * 256;             // 2048 float4
            int row = f >> 4, d = (f & 15) * 4;
            float4 v = X4[f];
            uint2 hv = make_uint2(pack_h2(__float2half_rn(v.x), __float2half_rn(v.y)),
                                  pack_h2(__float2half_rn(v.z), __float2half_rn(v.w)));
            *reinterpret_cast<uint2*>(smem + SM_A + row * ROWB + d * 2) = hv;
        }
        if (t < M_TILE) {                    // cols 64..79: 1.0,1.0 then zeros
            char* rp = smem + SM_A + t * ROWB;
            *reinterpret_cast<uint4*>(rp + 128) = make_uint4(0x3C003C00u, 0u, 0u, 0u);
            *reinterpret_cast<uint4*>(rp + 144) = make_uint4(0u, 0u, 0u, 0u);
        }
    }
    __syncthreads();

    // ---- preload A fragments (5 k-steps x 4 regs) ----
    uint32_t af[NUM_KS][4];
    {
        uint32_t aAddr = sb + SM_A + (uint32_t)(wr0 + (l & 15)) * ROWB + (uint32_t)(l >> 4) * 16;
#pragma unroll
        for (int ks = 0; ks < NUM_KS; ks++)
            LDSM4(af[ks][0], af[ks][1], af[ks][2], af[ks][3], aAddr + ks * 32);
    }

    // B lane offset within a 16-code group (x4: [n0-7,k0-7][n0-7,k8-15][n8-15,k0-7][n8-15,k8-15])
    const uint32_t bLane = (uint32_t)(l & 7) * ROWB + ((uint32_t)(l >> 3) & 1) * 16 +
                           ((uint32_t)(l >> 4) & 1) * (8 * ROWB);

    // top-2 state: row q = wr0 + (l>>2) and row q+8
    float bmA1 = -3.0e38f, bmA2 = -3.0e38f, bmB1 = -3.0e38f, bmB2 = -3.0e38f;
    int bkA = 0, bkB = 0;

    for (int c = 0; c < NUM_CHUNKS; c++) {
        if (c >= NUM_CHUNKS - 2) { CP_WAIT0(); } else { CP_WAIT1(); }
        __syncthreads();

        const uint32_t bufB = sb + SM_B + (uint32_t)(c & 1) * (CHUNK * ROWB);
        float acc[8][4];
#pragma unroll
        for (int nt = 0; nt < 8; nt++)
#pragma unroll
            for (int j = 0; j < 4; j++) acc[nt][j] = 0.f;

#pragma unroll
        for (int np = 0; np < 4; np++) {           // 16 codes per pair-group
            const uint32_t bBase = bufB + (uint32_t)np * (16 * ROWB) + bLane;
#pragma unroll
            for (int ks = 0; ks < NUM_KS; ks++) {
                uint32_t b0, b1, b2, b3;
                LDSM4(b0, b1, b2, b3, bBase + ks * 32);
                MMA16816(acc[np * 2],     af[ks], b0, b1);
                MMA16816(acc[np * 2 + 1], af[ks], b2, b3);
            }
        }
        __syncthreads();   // done reading buf (before refill)

        // refill this buffer with chunk c+2
        if (c + 2 < NUM_CHUNKS) {
            const uint4* s2 = reinterpret_cast<const uint4*>(g_Bg) + (size_t)(c + 2) * CHUNK * 10;
            uint32_t dstb = sb + SM_B + (uint32_t)(c & 1) * (CHUNK * ROWB);
            for (int idx = t; idx < CHUNK * 10; idx += 256) {
                int code = idx / 10, u = idx - code * 10;
                CP_ASYNC16(dstb + code * ROWB + u * 16, s2 + idx);
            }
            CP_COMMIT();
        }

        // ---- epilogue: running top-2 / argmax (k ascending; strict > keeps lowest k) ----
#pragma unroll
        for (int nt = 0; nt < 8; nt++) {
            int k0 = c * CHUNK + nt * 8 + (l & 3) * 2;
            float v0 = acc[nt][0], v1 = acc[nt][1], v2 = acc[nt][2], v3 = acc[nt][3];
            if (v0 > bmA1) { bmA2 = bmA1; bmA1 = v0; bkA = k0; }     else bmA2 = fmaxf(bmA2, v0);
            if (v1 > bmA1) { bmA2 = bmA1; bmA1 = v1; bkA = k0 + 1; } else bmA2 = fmaxf(bmA2, v1);
            if (v2 > bmB1) { bmB2 = bmB1; bmB1 = v2; bkB = k0; }     else bmB2 = fmaxf(bmB2, v2);
            if (v3 > bmB1) { bmB2 = bmB1; bmB1 = v3; bkB = k0 + 1; } else bmB2 = fmaxf(bmB2, v3);
        }
    }

    // ---- merge across the 4 lanes of each quad (same rows, disjoint cols) ----
#pragma unroll
    for (int off = 1; off <= 2; off <<= 1) {
        float o1, o2; int ok;
        o1 = __shfl_xor_sync(0xffffffffu, bmA1, off);
        o2 = __shfl_xor_sync(0xffffffffu, bmA2, off);
        ok = __shfl_xor_sync(0xffffffffu, bkA, off);
        {
            bool bw = (o1 > bmA1) || (o1 == bmA1 && ok < bkA);
            float n2 = fmaxf(fminf(bmA1, o1), fmaxf(bmA2, o2));
            if (bw) { bmA1 = o1; bkA = ok; }
            bmA2 = n2;
        }
        o1 = __shfl_xor_sync(0xffffffffu, bmB1, off);
        o2 = __shfl_xor_sync(0xffffffffu, bmB2, off);
        ok = __shfl_xor_sync(0xffffffffu, bkB, off);
        {
            bool bw = (o1 > bmB1) || (o1 == bmB1 && ok < bkB);
            float n2 = fmaxf(fminf(bmB1, o1), fmaxf(bmB2, o2));
            if (bw) { bmB1 = o1; bkB = ok; }
            bmB2 = n2;
        }
    }
    if ((l & 3) == 0) {
        int rowA = wr0 + (l >> 2);
        int rowB = rowA + 8;
        best_sh[rowA] = bkA;
        best_sh[rowB] = bkB;
        out_idx[m0 + rowA] = (float)bkA;
        out_idx[m0 + rowB] = (float)bkB;
        if (bmA1 - bmA2 <= TAU) { int a = atomicAdd(&g_namb, 1); g_amb_rows[a] = m0 + rowA; }
        if (bmB1 - bmB2 <= TAU) { int a = atomicAdd(&g_namb, 1); g_amb_rows[a] = m0 + rowB; }
    }
    __syncthreads();

    // ---- outputs: gather + residual ----
#pragma unroll
    for (int i = 0; i < (M_TILE * D_DIM) / 256; i++) {   // 32 iters
        int f = t + i * 256;
        int row = f >> 6, d = f & 63;
        int bk = best_sh[row];
        size_t g = (size_t)(m0 + row) * D_DIM + d;
        float cv = __ldg(&Cb[(size_t)bk * D_DIM + d]);
        float xv = __ldg(&X[g]);
        out_cb[g]  = cv;
        out_res[g] = __fsub_rn(xv, cv);
    }
}

// ---------------- Exact fallback (R3 arithmetic, coalesced d-major loads) ----------------
__global__ void __launch_bounds__(128)
vq_fallback_kernel(const float* __restrict__ X, const float* __restrict__ Cb,
                   float* __restrict__ out_idx, float* __restrict__ out_res,
                   float* __restrict__ out_cb) {
    __shared__ float xrow[D_DIM];
    __shared__ float xsq_s;
    __shared__ float rs[4];
    __shared__ int rk[4];
    const int t = threadIdx.x;
    const int n = g_namb;
    for (int j = blockIdx.x; j < n; j += gridDim.x) {
        const int row = g_amb_rows[j];
        __syncthreads();
        if (t < D_DIM) xrow[t] = X[(size_t)row * D_DIM + t];
        __syncthreads();
        if (t == 0) xsq_s = sq_sum_tree64(xrow);
        __syncthreads();
        const float xsq = xsq_s;
        float bs = 3.0e38f;
        int bk = 0;
#pragma unroll
        for (int c = 0; c < K_CODES / 128; c++) {
            int k = c * 128 + t;
            float acc = 0.f;
            // identical value sequence to R3 (d ascending), but coalesced via g_Ct
#pragma unroll 8
            for (int d = 0; d < D_DIM; d++)
                acc = fmaf(xrow[d], __ldg(&g_Ct[d * K_CODES + k]), acc);
            float s = __fadd_rn(__fsub_rn(xsq, 2.0f * acc), g_csq[k]);
            if (s < bs) { bs = s; bk = k; }   // k ascending: strict < keeps lowest
        }
#pragma unroll
        for (int off = 16; off; off >>= 1) {
            float os = __shfl_xor_sync(0xffffffffu, bs, off);
            int ok = __shfl_xor_sync(0xffffffffu, bk, off);
            if (os < bs || (os == bs && ok < bk)) { bs = os; bk = ok; }
        }
        if ((t & 31) == 0) { rs[t >> 5] = bs; rk[t >> 5] = bk; }
        __syncthreads();
        if (t == 0) {
            for (int wi = 1; wi < 4; wi++)
                if (rs[wi] < rs[0] || (rs[wi] == rs[0] && rk[wi] < rk[0])) {
                    rs[0] = rs[wi]; rk[0] = rk[wi];
                }
            out_idx[row] = (float)rk[0];
        }
        __syncthreads();
        const int k1 = rk[0];
        if (t < D_DIM) {
            size_t g = (size_t)row * D_DIM + t;
            float cv = __ldg(&Cb[(size_t)k1 * D_DIM + t]);
            out_cb[g]  = cv;
            out_res[g] = __fsub_rn(xrow[t], cv);
        }
    }
}

// ---------------- Launch ----------------
extern "C" void kernel_launch(void* const* d_in, const int* in_sizes, int n_in,
                              void* d_out, int out_size) {
    const float* X = (const float*)d_in[0];
    const float* C = (const float*)d_in[1];
    float* out_idx = (float*)d_out;
    float* out_res = out_idx + N_ROWS;
    float* out_cb  = out_res + (size_t)N_ROWS * D_DIM;

    cudaFuncSetAttribute(vq_screen_kernel,
                         cudaFuncAttributeMaxDynamicSharedMemorySize, SM_TOTAL);

    zero_kernel<<<1, 1>>>();
    prep_kernel<<<(K_CODES + 255) / 256, 256>>>(C);
    vq_screen_kernel<<<N_ROWS / M_TILE, 256, SM_TOTAL>>>(X, C, out_idx, out_res, out_cb);
    vq_fallback_kernel<<<2048, 128>>>(X, C, out_idx, out_res, out_cb);
}